// round 14
// baseline (speedup 1.0000x reference)
#include <cuda_runtime.h>
#include <cuda_bf16.h>
#include <cuda_fp16.h>
#include <math.h>
#include <stdint.h>

#define NN 50000
#define EE 1600000
#define FF 256
#define KHOP 3
#define GN 256
#define TOTN (KHOP * NN)          // 150000
#define SCAN_BLOCKS ((TOTN + 1023) / 1024)   // 147

// ---------------- scratch (device globals; no allocations allowed) ----------------
__device__ float g_u[KHOP * FF];
__device__ float g_v[KHOP * FF];
__device__ float4 g_tsrc[KHOP * NN];   // (s_src, exp(-s_src), exp(-0.2*s_src), 0)
__device__ float4 g_tdst[KHOP * NN];   // (s_dst, exp(-s_dst), exp(-0.2*s_dst), 0)
__device__ int   g_deg[KHOP * NN];
__device__ int   g_ptr[KHOP * NN];
__device__ int   g_fill[KHOP * NN];
__device__ int   g_bsum[SCAN_BLOCKS];
__device__ int   g_boff[SCAN_BLOCKS];
__device__ uint32_t g_csr[(size_t)KHOP * EE + 32];   // packed: dst(lo16) | fp16-weight(hi16)
__device__ __half g_Yh[(size_t)KHOP * NN * FF];      // Y_z = X @ W_z, fp16
__device__ __half g_Xh[(size_t)NN * FF];             // X in fp16
__device__ __half g_Wth[KHOP * FF * GN];             // W transposed [z][n][k], fp16

__device__ __forceinline__ float elu1(float x) { return x > 0.f ? x : expm1f(x); }

// ---------------- small kernels (pipeline front) ----------------

__global__ void zero_kernel() {
    int i = blockIdx.x * blockDim.x + threadIdx.x;
    if (i < TOTN) g_deg[i] = 0;
}

__global__ void uv_kernel(const float* __restrict__ W, const float* __restrict__ a) {
    int z = blockIdx.x;
    int k = threadIdx.x;
    const float* wrow = W + (size_t)(z * FF + k) * GN;
    const float* au = a + z * 2 * FF;
    const float* av = au + FF;
    float u = 0.f, v = 0.f;
    #pragma unroll 8
    for (int j = 0; j < FF; j++) {
        float w = wrow[j];
        u = fmaf(w, au[j], u);
        v = fmaf(w, av[j], v);
    }
    g_u[z * FF + k] = u;
    g_v[z * FF + k] = v;
}

__device__ __forceinline__ uint32_t pkh2(float a, float b) {
    __half2 t = __floats2half2_rn(a, b);
    return *(uint32_t*)&t;
}

// fused: per-hop score tables + fp16 conversion of X.
// warp per node; lane owns feature PAIRS {2*lane + 64*j} (2-way smem conflicts only).
__global__ void __launch_bounds__(256) scores_convX_kernel(const float* __restrict__ X) {
    __shared__ float su[KHOP][FF];
    __shared__ float sv[KHOP][FF];
    int tid = threadIdx.x;
    for (int i = tid; i < KHOP * FF; i += 256) {
        su[i / FF][i % FF] = g_u[i];
        sv[i / FF][i % FF] = g_v[i];
    }
    __syncthreads();
    int warp = tid >> 5, lane = tid & 31;
    int n = blockIdx.x * 8 + warp;
    if (n >= NN) return;
    const int f0 = lane * 2;
    float2 xp[4];
    #pragma unroll
    for (int j = 0; j < 4; j++) {
        xp[j] = *(const float2*)(X + (size_t)n * FF + f0 + j * 64);
        *(uint32_t*)(g_Xh + (size_t)n * FF + f0 + j * 64) = pkh2(xp[j].x, xp[j].y);
    }
    #pragma unroll
    for (int z = 0; z < KHOP; z++) {
        float du = 0.f, dv = 0.f;
        #pragma unroll
        for (int j = 0; j < 4; j++) {
            int f = f0 + j * 64;
            du = fmaf(xp[j].x, su[z][f], du);
            du = fmaf(xp[j].y, su[z][f + 1], du);
            dv = fmaf(xp[j].x, sv[z][f], dv);
            dv = fmaf(xp[j].y, sv[z][f + 1], dv);
        }
        #pragma unroll
        for (int off = 16; off > 0; off >>= 1) {
            du += __shfl_xor_sync(0xFFFFFFFFu, du, off);
            dv += __shfl_xor_sync(0xFFFFFFFFu, dv, off);
        }
        if (lane == 0) {
            g_tsrc[z * NN + n] = make_float4(du, expf(-du), expf(-0.2f * du), 0.f);
            g_tdst[z * NN + n] = make_float4(dv, expf(-dv), expf(-0.2f * dv), 0.f);
        }
    }
}

// 4 edges per thread via int4 (EE divisible by 4)
__global__ void hist_kernel(const int* __restrict__ kel) {
    int z = blockIdx.y;
    int e = (blockIdx.x * 256 + threadIdx.x) * 4;
    if (e >= EE) return;
    int4 s = __ldcs((const int4*)(kel + (size_t)z * 2 * EE + e));
    atomicAdd(&g_deg[z * NN + s.x], 1);
    atomicAdd(&g_deg[z * NN + s.y], 1);
    atomicAdd(&g_deg[z * NN + s.z], 1);
    atomicAdd(&g_deg[z * NN + s.w], 1);
}

// ---- 3-phase parallel scan over the whole 150K degree array ----
__global__ void __launch_bounds__(1024) scanA_kernel() {
    __shared__ int wsum[32];
    int b = blockIdx.x, tid = threadIdx.x, lane = tid & 31, wid = tid >> 5;
    int i = b * 1024 + tid;
    int v = (i < TOTN) ? g_deg[i] : 0;
    int x = v;
    #pragma unroll
    for (int off = 1; off < 32; off <<= 1) {
        int t = __shfl_up_sync(0xFFFFFFFFu, x, off);
        if (lane >= off) x += t;
    }
    if (lane == 31) wsum[wid] = x;
    __syncthreads();
    if (wid == 0) {
        int s = wsum[lane];
        #pragma unroll
        for (int off = 1; off < 32; off <<= 1) {
            int t = __shfl_up_sync(0xFFFFFFFFu, s, off);
            if (lane >= off) s += t;
        }
        wsum[lane] = s;
    }
    __syncthreads();
    int woff = wid ? wsum[wid - 1] : 0;
    if (i < TOTN) g_ptr[i] = woff + x - v;
    if (tid == 1023) g_bsum[b] = wsum[31];
}

__global__ void __launch_bounds__(256) scanB_kernel() {
    __shared__ int wsum[8];
    int tid = threadIdx.x, lane = tid & 31, wid = tid >> 5;
    int v = (tid < SCAN_BLOCKS) ? g_bsum[tid] : 0;
    int x = v;
    #pragma unroll
    for (int off = 1; off < 32; off <<= 1) {
        int t = __shfl_up_sync(0xFFFFFFFFu, x, off);
        if (lane >= off) x += t;
    }
    if (lane == 31) wsum[wid] = x;
    __syncthreads();
    if (wid == 0 && lane < 8) {
        int s = wsum[lane];
        #pragma unroll
        for (int off = 1; off < 8; off <<= 1) {
            int t = __shfl_up_sync(0xFFu, s, off);
            if (lane >= off) s += t;
        }
        wsum[lane] = s;
    }
    __syncthreads();
    int woff = wid ? wsum[wid - 1] : 0;
    if (tid < SCAN_BLOCKS) g_boff[tid] = woff + x - v;
}

__global__ void __launch_bounds__(1024) scanC_kernel() {
    int b = blockIdx.x;
    int i = b * 1024 + threadIdx.x;
    if (i >= TOTN) return;
    int z = (i >= 2 * NN) ? 2 : (i >= NN) ? 1 : 0;
    int val = g_ptr[i] + g_boff[b] - z * EE;
    g_ptr[i] = val;
    g_fill[i] = val;
}

// CSR build: 4 edges/thread; packed 4B entries (dst lo16 | fp16 weight hi16)
__global__ void build_kernel(const int* __restrict__ kel) {
    int z = blockIdx.y;
    int e = (blockIdx.x * 256 + threadIdx.x) * 4;
    if (e >= EE) return;
    int4 s4 = __ldcs((const int4*)(kel + (size_t)z * 2 * EE + e));
    int4 d4 = __ldcs((const int4*)(kel + (size_t)z * 2 * EE + EE + e));
    const int srcs[4] = {s4.x, s4.y, s4.z, s4.w};
    const int dsts[4] = {d4.x, d4.y, d4.z, d4.w};
    #pragma unroll
    for (int q = 0; q < 4; q++) {
        float4 ts = g_tsrc[z * NN + srcs[q]];
        float4 td = g_tdst[z * NN + dsts[q]];
        float w = (ts.x + td.x > 0.f) ? ts.y * td.y : ts.z * td.z;
        uint32_t hw = (uint32_t)__half_as_ushort(__float2half_rn(w));
        uint32_t packed = (uint32_t)dsts[q] | (hw << 16);
        int idx = atomicAdd(&g_fill[z * NN + srcs[q]], 1);
        __stcs(&g_csr[(size_t)z * EE + idx], packed);
    }
}

__global__ void __launch_bounds__(256) convW_kernel(const float* __restrict__ W) {
    int idx = blockIdx.x * 256 + threadIdx.x;
    if (idx >= KHOP * FF * GN) return;
    int z = idx >> 16;
    int rem = idx & 65535;
    int k = rem >> 8;
    int n = rem & 255;
    float w = W[(size_t)(z * FF + k) * GN + n];
    g_Wth[z * 65536 + n * 256 + k] = __float2half_rn(w);
}

// ---------------- mma.sync fp16 GEMM (base-ISA HMMA; sm_103-safe) ----------------

#define SAW 40   // smem row pitch in halfs (80 B: 16B-aligned, conflict-free frag reads)

__device__ __forceinline__ void mma16816h(float* c, const uint32_t* a, const uint32_t* b) {
    asm volatile(
        "mma.sync.aligned.m16n8k16.row.col.f32.f16.f16.f32 "
        "{%0,%1,%2,%3}, {%4,%5,%6,%7}, {%8,%9}, {%0,%1,%2,%3};"
        : "+f"(c[0]), "+f"(c[1]), "+f"(c[2]), "+f"(c[3])
        : "r"(a[0]), "r"(a[1]), "r"(a[2]), "r"(a[3]), "r"(b[0]), "r"(b[1]));
}

__global__ void __launch_bounds__(256) gemm_mma_kernel() {
    __shared__ __half sA[128 * SAW];
    __shared__ __half sB[128 * SAW];

    const int tid = threadIdx.x;
    const int wid = tid >> 5, lane = tid & 31;
    const int g = lane >> 2, tg = lane & 3;
    const int warp_m = wid >> 2;
    const int warp_n = wid & 3;
    const int rowBase = blockIdx.x * 128;
    const int colBase = blockIdx.y * 128;
    const int z = blockIdx.z;

    const __half* Wth = g_Wth + (size_t)z * 65536;
    __half* Yh = g_Yh + (size_t)z * NN * FF;

    float c[4][4][4];
    #pragma unroll
    for (int mt = 0; mt < 4; mt++)
        #pragma unroll
        for (int nt = 0; nt < 4; nt++)
            #pragma unroll
            for (int q = 0; q < 4; q++) c[mt][nt][q] = 0.f;

    for (int kc = 0; kc < 8; kc++) {
        const int k0g = kc * 32;
        #pragma unroll
        for (int it = 0; it < 2; it++) {
            int q = tid + it * 256;
            int r = q >> 2, s = q & 3;
            int row_g = rowBase + r;
            uint4 va = make_uint4(0, 0, 0, 0);
            if (row_g < NN) va = *(const uint4*)(g_Xh + (size_t)row_g * FF + k0g + s * 8);
            *(uint4*)(sA + r * SAW + s * 8) = va;
        }
        #pragma unroll
        for (int it = 0; it < 2; it++) {
            int q = tid + it * 256;
            int r = q >> 2, s = q & 3;
            *(uint4*)(sB + r * SAW + s * 8) =
                *(const uint4*)(Wth + (size_t)(colBase + r) * 256 + k0g + s * 8);
        }
        __syncthreads();

        #pragma unroll
        for (int ks = 0; ks < 2; ks++) {
            const int k0 = ks * 16;
            uint32_t ah[4][4];
            #pragma unroll
            for (int mt = 0; mt < 4; mt++) {
                int r0 = warp_m * 64 + mt * 16 + g;
                int kk = k0 + tg * 2;
                ah[mt][0] = *(const uint32_t*)(sA + r0 * SAW + kk);
                ah[mt][1] = *(const uint32_t*)(sA + (r0 + 8) * SAW + kk);
                ah[mt][2] = *(const uint32_t*)(sA + r0 * SAW + kk + 8);
                ah[mt][3] = *(const uint32_t*)(sA + (r0 + 8) * SAW + kk + 8);
            }
            uint32_t bh[4][2];
            #pragma unroll
            for (int nt = 0; nt < 4; nt++) {
                int n0 = warp_n * 32 + nt * 8 + g;
                int kk = k0 + tg * 2;
                bh[nt][0] = *(const uint32_t*)(sB + n0 * SAW + kk);
                bh[nt][1] = *(const uint32_t*)(sB + n0 * SAW + kk + 8);
            }
            #pragma unroll
            for (int mt = 0; mt < 4; mt++)
                #pragma unroll
                for (int nt = 0; nt < 4; nt++)
                    mma16816h(c[mt][nt], ah[mt], bh[nt]);
        }
        __syncthreads();
    }

    #pragma unroll
    for (int mt = 0; mt < 4; mt++) {
        int r0 = rowBase + warp_m * 64 + mt * 16 + g;
        #pragma unroll
        for (int nt = 0; nt < 4; nt++) {
            int col = colBase + warp_n * 32 + nt * 8 + tg * 2;
            if (r0 < NN)
                *(uint32_t*)(Yh + (size_t)r0 * GN + col) = pkh2(c[mt][nt][0], c[mt][nt][1]);
            if (r0 + 8 < NN)
                *(uint32_t*)(Yh + (size_t)(r0 + 8) * GN + col) = pkh2(c[mt][nt][2], c[mt][nt][3]);
        }
    }
}

// ---------------- fused 3-hop aggregation, feature-split into 2 passes ----------------
// packed CSR: one 4B entry per edge; single shuffle broadcast per edge-step
__global__ void __launch_bounds__(256) aggregate_fused_kernel(float* __restrict__ out) {
    const int wid = threadIdx.x >> 5, lane = threadIdx.x & 31;
    const int n = blockIdx.x * 8 + wid;
    const int p = blockIdx.y;                    // feature half
    if (n >= NN) return;
    const int fo = p * 128 + lane * 4;

    float tot[4] = {0.f, 0.f, 0.f, 0.f};

    #pragma unroll
    for (int z = 0; z < KHOP; z++) {
        const int start = g_ptr[z * NN + n];
        const int d     = g_deg[z * NN + n];
        const uint32_t* __restrict__ ce = g_csr + (size_t)z * EE + start;
        const __half* __restrict__ Yz = g_Yh + (size_t)z * NN * FF + fo;

        float acc[4] = {0.f, 0.f, 0.f, 0.f};
        float accw = 0.f;

        for (int base = 0; base < d; base += 32) {
            int cnt = min(32, d - base);
            uint32_t e = __ldcs(&ce[base + lane]);   // streaming: don't evict hot Y
            #pragma unroll 8
            for (int k = 0; k < cnt; k++) {
                uint32_t pk = __shfl_sync(0xFFFFFFFFu, e, k);
                int   dst = (int)(pk & 0xFFFFu);
                float w   = __half2float(__ushort_as_half((unsigned short)(pk >> 16)));
                accw += w;
                uint2 v = *(const uint2*)(Yz + (size_t)dst * FF);
                float2 f0 = __half22float2(*(__half2*)&v.x);
                float2 f1 = __half22float2(*(__half2*)&v.y);
                acc[0] = fmaf(w, f0.x, acc[0]);
                acc[1] = fmaf(w, f0.y, acc[1]);
                acc[2] = fmaf(w, f1.x, acc[2]);
                acc[3] = fmaf(w, f1.y, acc[3]);
            }
        }
        const float coef = (z == 0) ? 0.5f : (z == 1) ? 0.25f : 0.125f;
        float s = coef / accw;
        #pragma unroll
        for (int t = 0; t < 4; t++) tot[t] = fmaf(acc[t], s, tot[t]);
    }

    float4 o = make_float4(elu1(tot[0]), elu1(tot[1]), elu1(tot[2]), elu1(tot[3]));
    __stcs((float4*)(out + (size_t)n * FF + fo), o);
}

// ---------------- launch (serial; fork proved worthless — shared LTS bound) --------
extern "C" void kernel_launch(void* const* d_in, const int* in_sizes, int n_in,
                              void* d_out, int out_size) {
    const float* X   = (const float*)d_in[0];
    const int*   kel = (const int*)d_in[1];
    const float* W   = (const float*)d_in[2];
    const float* a   = (const float*)d_in[3];
    float* out = (float*)d_out;

    zero_kernel<<<(TOTN + 255) / 256, 256>>>();
    uv_kernel<<<KHOP, 256>>>(W, a);
    convW_kernel<<<(KHOP * FF * GN + 255) / 256, 256>>>(W);
    scores_convX_kernel<<<(NN + 7) / 8, 256>>>(X);
    hist_kernel<<<dim3((EE / 4 + 255) / 256, KHOP), 256>>>(kel);
    gemm_mma_kernel<<<dim3((NN + 127) / 128, GN / 128, KHOP), 256>>>();
    scanA_kernel<<<SCAN_BLOCKS, 1024>>>();
    scanB_kernel<<<1, 256>>>();
    scanC_kernel<<<SCAN_BLOCKS, 1024>>>();
    build_kernel<<<dim3((EE / 4 + 255) / 256, KHOP), 256>>>(kel);
    aggregate_fused_kernel<<<dim3((NN + 7) / 8, 2), 256>>>(out);
}

// round 15
// speedup vs baseline: 1.0857x; 1.0857x over previous
#include <cuda_runtime.h>
#include <cuda_bf16.h>
#include <cuda_fp16.h>
#include <math.h>
#include <stdint.h>

#define NN 50000
#define EE 1600000
#define FF 256
#define KHOP 3
#define GN 256
#define TOTN (KHOP * NN)          // 150000
#define SCAN_BLOCKS ((TOTN + 1023) / 1024)   // 147

// ---------------- scratch (device globals; no allocations allowed) ----------------
__device__ float g_u[KHOP * FF];
__device__ float g_v[KHOP * FF];
__device__ float g_s_src[KHOP * NN];
__device__ float g_s_dst[KHOP * NN];
__device__ int   g_deg[KHOP * NN];
__device__ int   g_ptr[KHOP * NN];
__device__ int   g_fill[KHOP * NN];
__device__ int   g_bsum[SCAN_BLOCKS];
__device__ int   g_boff[SCAN_BLOCKS];
__device__ int2  g_csr[(size_t)KHOP * EE + 32];      // (dst, w-as-int); +32 pad for warp over-read
__device__ __half g_Yh[(size_t)KHOP * NN * FF];      // Y_z = X @ W_z, fp16
__device__ __half g_Xh[(size_t)NN * FF];             // X in fp16
__device__ __half g_Wth[KHOP * FF * GN];             // W transposed [z][n][k], fp16

__device__ __forceinline__ float elu1(float x) { return x > 0.f ? x : expm1f(x); }

// ---------------- small kernels (pipeline front) ----------------

__global__ void zero_kernel() {
    int i = blockIdx.x * blockDim.x + threadIdx.x;
    if (i < TOTN) g_deg[i] = 0;
}

__global__ void uv_kernel(const float* __restrict__ W, const float* __restrict__ a) {
    int z = blockIdx.x;
    int k = threadIdx.x;
    const float* wrow = W + (size_t)(z * FF + k) * GN;
    const float* au = a + z * 2 * FF;
    const float* av = au + FF;
    float u = 0.f, v = 0.f;
    #pragma unroll 8
    for (int j = 0; j < FF; j++) {
        float w = wrow[j];
        u = fmaf(w, au[j], u);
        v = fmaf(w, av[j], v);
    }
    g_u[z * FF + k] = u;
    g_v[z * FF + k] = v;
}

__device__ __forceinline__ uint32_t pkh2(float a, float b) {
    __half2 t = __floats2half2_rn(a, b);
    return *(uint32_t*)&t;
}

// fused: per-hop s_src/s_dst + fp16 conversion of X.
// warp per node; lane owns feature PAIRS {2*lane + 64*j} (2-way smem conflicts only).
__global__ void __launch_bounds__(256) scores_convX_kernel(const float* __restrict__ X) {
    __shared__ float su[KHOP][FF];
    __shared__ float sv[KHOP][FF];
    int tid = threadIdx.x;
    for (int i = tid; i < KHOP * FF; i += 256) {
        su[i / FF][i % FF] = g_u[i];
        sv[i / FF][i % FF] = g_v[i];
    }
    __syncthreads();
    int warp = tid >> 5, lane = tid & 31;
    int n = blockIdx.x * 8 + warp;
    if (n >= NN) return;
    const int f0 = lane * 2;
    float2 xp[4];
    #pragma unroll
    for (int j = 0; j < 4; j++) {
        xp[j] = *(const float2*)(X + (size_t)n * FF + f0 + j * 64);
        *(uint32_t*)(g_Xh + (size_t)n * FF + f0 + j * 64) = pkh2(xp[j].x, xp[j].y);
    }
    #pragma unroll
    for (int z = 0; z < KHOP; z++) {
        float du = 0.f, dv = 0.f;
        #pragma unroll
        for (int j = 0; j < 4; j++) {
            int f = f0 + j * 64;
            du = fmaf(xp[j].x, su[z][f], du);
            du = fmaf(xp[j].y, su[z][f + 1], du);
            dv = fmaf(xp[j].x, sv[z][f], dv);
            dv = fmaf(xp[j].y, sv[z][f + 1], dv);
        }
        #pragma unroll
        for (int off = 16; off > 0; off >>= 1) {
            du += __shfl_xor_sync(0xFFFFFFFFu, du, off);
            dv += __shfl_xor_sync(0xFFFFFFFFu, dv, off);
        }
        if (lane == 0) {
            g_s_src[z * NN + n] = du;
            g_s_dst[z * NN + n] = dv;
        }
    }
}

// 4 edges per thread via int4 (EE divisible by 4)
__global__ void hist_kernel(const int* __restrict__ kel) {
    int z = blockIdx.y;
    int e = (blockIdx.x * 256 + threadIdx.x) * 4;
    if (e >= EE) return;
    int4 s = __ldcs((const int4*)(kel + (size_t)z * 2 * EE + e));
    atomicAdd(&g_deg[z * NN + s.x], 1);
    atomicAdd(&g_deg[z * NN + s.y], 1);
    atomicAdd(&g_deg[z * NN + s.z], 1);
    atomicAdd(&g_deg[z * NN + s.w], 1);
}

// ---- 3-phase parallel scan over the whole 150K degree array ----
__global__ void __launch_bounds__(1024) scanA_kernel() {
    __shared__ int wsum[32];
    int b = blockIdx.x, tid = threadIdx.x, lane = tid & 31, wid = tid >> 5;
    int i = b * 1024 + tid;
    int v = (i < TOTN) ? g_deg[i] : 0;
    int x = v;
    #pragma unroll
    for (int off = 1; off < 32; off <<= 1) {
        int t = __shfl_up_sync(0xFFFFFFFFu, x, off);
        if (lane >= off) x += t;
    }
    if (lane == 31) wsum[wid] = x;
    __syncthreads();
    if (wid == 0) {
        int s = wsum[lane];
        #pragma unroll
        for (int off = 1; off < 32; off <<= 1) {
            int t = __shfl_up_sync(0xFFFFFFFFu, s, off);
            if (lane >= off) s += t;
        }
        wsum[lane] = s;
    }
    __syncthreads();
    int woff = wid ? wsum[wid - 1] : 0;
    if (i < TOTN) g_ptr[i] = woff + x - v;
    if (tid == 1023) g_bsum[b] = wsum[31];
}

__global__ void __launch_bounds__(256) scanB_kernel() {
    __shared__ int wsum[8];
    int tid = threadIdx.x, lane = tid & 31, wid = tid >> 5;
    int v = (tid < SCAN_BLOCKS) ? g_bsum[tid] : 0;
    int x = v;
    #pragma unroll
    for (int off = 1; off < 32; off <<= 1) {
        int t = __shfl_up_sync(0xFFFFFFFFu, x, off);
        if (lane >= off) x += t;
    }
    if (lane == 31) wsum[wid] = x;
    __syncthreads();
    if (wid == 0 && lane < 8) {
        int s = wsum[lane];
        #pragma unroll
        for (int off = 1; off < 8; off <<= 1) {
            int t = __shfl_up_sync(0xFFu, s, off);
            if (lane >= off) s += t;
        }
        wsum[lane] = s;
    }
    __syncthreads();
    int woff = wid ? wsum[wid - 1] : 0;
    if (tid < SCAN_BLOCKS) g_boff[tid] = woff + x - v;
}

__global__ void __launch_bounds__(1024) scanC_kernel() {
    int b = blockIdx.x;
    int i = b * 1024 + threadIdx.x;
    if (i >= TOTN) return;
    int z = (i >= 2 * NN) ? 2 : (i >= NN) ? 1 : 0;
    int val = g_ptr[i] + g_boff[b] - z * EE;
    g_ptr[i] = val;
    g_fill[i] = val;
}

// CSR build: 4 edges/thread, int4 index loads, expf weights, int2 entries
__global__ void build_kernel(const int* __restrict__ kel) {
    int z = blockIdx.y;
    int e = (blockIdx.x * 256 + threadIdx.x) * 4;
    if (e >= EE) return;
    int4 s4 = __ldcs((const int4*)(kel + (size_t)z * 2 * EE + e));
    int4 d4 = __ldcs((const int4*)(kel + (size_t)z * 2 * EE + EE + e));
    const int srcs[4] = {s4.x, s4.y, s4.z, s4.w};
    const int dsts[4] = {d4.x, d4.y, d4.z, d4.w};
    #pragma unroll
    for (int q = 0; q < 4; q++) {
        float sc = g_s_src[z * NN + srcs[q]] + g_s_dst[z * NN + dsts[q]];
        float l = sc > 0.f ? sc : 0.2f * sc;       // leaky_relu(alpha=0.2)
        float w = expf(-l);
        int idx = atomicAdd(&g_fill[z * NN + srcs[q]], 1);
        __stcs(&g_csr[(size_t)z * EE + idx], make_int2(dsts[q], __float_as_int(w)));
    }
}

__global__ void __launch_bounds__(256) convW_kernel(const float* __restrict__ W) {
    int idx = blockIdx.x * 256 + threadIdx.x;
    if (idx >= KHOP * FF * GN) return;
    int z = idx >> 16;
    int rem = idx & 65535;
    int k = rem >> 8;
    int n = rem & 255;
    float w = W[(size_t)(z * FF + k) * GN + n];
    g_Wth[z * 65536 + n * 256 + k] = __float2half_rn(w);
}

// ---------------- mma.sync fp16 GEMM (base-ISA HMMA; sm_103-safe) ----------------

#define SAW 40   // smem row pitch in halfs (80 B: 16B-aligned, conflict-free frag reads)

__device__ __forceinline__ void mma16816h(float* c, const uint32_t* a, const uint32_t* b) {
    asm volatile(
        "mma.sync.aligned.m16n8k16.row.col.f32.f16.f16.f32 "
        "{%0,%1,%2,%3}, {%4,%5,%6,%7}, {%8,%9}, {%0,%1,%2,%3};"
        : "+f"(c[0]), "+f"(c[1]), "+f"(c[2]), "+f"(c[3])
        : "r"(a[0]), "r"(a[1]), "r"(a[2]), "r"(a[3]), "r"(b[0]), "r"(b[1]));
}

__global__ void __launch_bounds__(256) gemm_mma_kernel() {
    __shared__ __half sA[128 * SAW];
    __shared__ __half sB[128 * SAW];

    const int tid = threadIdx.x;
    const int wid = tid >> 5, lane = tid & 31;
    const int g = lane >> 2, tg = lane & 3;
    const int warp_m = wid >> 2;
    const int warp_n = wid & 3;
    const int rowBase = blockIdx.x * 128;
    const int colBase = blockIdx.y * 128;
    const int z = blockIdx.z;

    const __half* Wth = g_Wth + (size_t)z * 65536;
    __half* Yh = g_Yh + (size_t)z * NN * FF;

    float c[4][4][4];
    #pragma unroll
    for (int mt = 0; mt < 4; mt++)
        #pragma unroll
        for (int nt = 0; nt < 4; nt++)
            #pragma unroll
            for (int q = 0; q < 4; q++) c[mt][nt][q] = 0.f;

    for (int kc = 0; kc < 8; kc++) {
        const int k0g = kc * 32;
        #pragma unroll
        for (int it = 0; it < 2; it++) {
            int q = tid + it * 256;
            int r = q >> 2, s = q & 3;
            int row_g = rowBase + r;
            uint4 va = make_uint4(0, 0, 0, 0);
            if (row_g < NN) va = *(const uint4*)(g_Xh + (size_t)row_g * FF + k0g + s * 8);
            *(uint4*)(sA + r * SAW + s * 8) = va;
        }
        #pragma unroll
        for (int it = 0; it < 2; it++) {
            int q = tid + it * 256;
            int r = q >> 2, s = q & 3;
            *(uint4*)(sB + r * SAW + s * 8) =
                *(const uint4*)(Wth + (size_t)(colBase + r) * 256 + k0g + s * 8);
        }
        __syncthreads();

        #pragma unroll
        for (int ks = 0; ks < 2; ks++) {
            const int k0 = ks * 16;
            uint32_t ah[4][4];
            #pragma unroll
            for (int mt = 0; mt < 4; mt++) {
                int r0 = warp_m * 64 + mt * 16 + g;
                int kk = k0 + tg * 2;
                ah[mt][0] = *(const uint32_t*)(sA + r0 * SAW + kk);
                ah[mt][1] = *(const uint32_t*)(sA + (r0 + 8) * SAW + kk);
                ah[mt][2] = *(const uint32_t*)(sA + r0 * SAW + kk + 8);
                ah[mt][3] = *(const uint32_t*)(sA + (r0 + 8) * SAW + kk + 8);
            }
            uint32_t bh[4][2];
            #pragma unroll
            for (int nt = 0; nt < 4; nt++) {
                int n0 = warp_n * 32 + nt * 8 + g;
                int kk = k0 + tg * 2;
                bh[nt][0] = *(const uint32_t*)(sB + n0 * SAW + kk);
                bh[nt][1] = *(const uint32_t*)(sB + n0 * SAW + kk + 8);
            }
            #pragma unroll
            for (int mt = 0; mt < 4; mt++)
                #pragma unroll
                for (int nt = 0; nt < 4; nt++)
                    mma16816h(c[mt][nt], ah[mt], bh[nt]);
        }
        __syncthreads();
    }

    #pragma unroll
    for (int mt = 0; mt < 4; mt++) {
        int r0 = rowBase + warp_m * 64 + mt * 16 + g;
        #pragma unroll
        for (int nt = 0; nt < 4; nt++) {
            int col = colBase + warp_n * 32 + nt * 8 + tg * 2;
            if (r0 < NN)
                *(uint32_t*)(Yh + (size_t)r0 * GN + col) = pkh2(c[mt][nt][0], c[mt][nt][1]);
            if (r0 + 8 < NN)
                *(uint32_t*)(Yh + (size_t)(r0 + 8) * GN + col) = pkh2(c[mt][nt][2], c[mt][nt][3]);
        }
    }
}

// ---------------- fused 3-hop aggregation, feature-split into 2 passes ----------------
// int2 CSR: two independent shuffles per edge feed FMAs directly (no cvt in chain)
__global__ void __launch_bounds__(256) aggregate_fused_kernel(float* __restrict__ out) {
    const int wid = threadIdx.x >> 5, lane = threadIdx.x & 31;
    const int n = blockIdx.x * 8 + wid;
    const int p = blockIdx.y;                    // feature half
    if (n >= NN) return;
    const int fo = p * 128 + lane * 4;

    float tot[4] = {0.f, 0.f, 0.f, 0.f};

    #pragma unroll
    for (int z = 0; z < KHOP; z++) {
        const int start = g_ptr[z * NN + n];
        const int d     = g_deg[z * NN + n];
        const int2* __restrict__ ce = g_csr + (size_t)z * EE + start;
        const __half* __restrict__ Yz = g_Yh + (size_t)z * NN * FF + fo;

        float acc[4] = {0.f, 0.f, 0.f, 0.f};
        float accw = 0.f;

        for (int base = 0; base < d; base += 32) {
            int cnt = min(32, d - base);
            int2 e = __ldcs(&ce[base + lane]);   // streaming: don't evict hot Y
            #pragma unroll 8
            for (int k = 0; k < cnt; k++) {
                int   dst = __shfl_sync(0xFFFFFFFFu, e.x, k);
                float w   = __int_as_float(__shfl_sync(0xFFFFFFFFu, e.y, k));
                accw += w;
                uint2 v = *(const uint2*)(Yz + (size_t)dst * FF);
                float2 f0 = __half22float2(*(__half2*)&v.x);
                float2 f1 = __half22float2(*(__half2*)&v.y);
                acc[0] = fmaf(w, f0.x, acc[0]);
                acc[1] = fmaf(w, f0.y, acc[1]);
                acc[2] = fmaf(w, f1.x, acc[2]);
                acc[3] = fmaf(w, f1.y, acc[3]);
            }
        }
        const float coef = (z == 0) ? 0.5f : (z == 1) ? 0.25f : 0.125f;
        float s = coef / accw;
        #pragma unroll
        for (int t = 0; t < 4; t++) tot[t] = fmaf(acc[t], s, tot[t]);
    }

    float4 o = make_float4(elu1(tot[0]), elu1(tot[1]), elu1(tot[2]), elu1(tot[3]));
    __stcs((float4*)(out + (size_t)n * FF + fo), o);
}

// ---------------- launch (serial; fork proved worthless — shared LTS bound) --------
extern "C" void kernel_launch(void* const* d_in, const int* in_sizes, int n_in,
                              void* d_out, int out_size) {
    const float* X   = (const float*)d_in[0];
    const int*   kel = (const int*)d_in[1];
    const float* W   = (const float*)d_in[2];
    const float* a   = (const float*)d_in[3];
    float* out = (float*)d_out;

    zero_kernel<<<(TOTN + 255) / 256, 256>>>();
    uv_kernel<<<KHOP, 256>>>(W, a);
    convW_kernel<<<(KHOP * FF * GN + 255) / 256, 256>>>(W);
    scores_convX_kernel<<<(NN + 7) / 8, 256>>>(X);
    hist_kernel<<<dim3((EE / 4 + 255) / 256, KHOP), 256>>>(kel);
    gemm_mma_kernel<<<dim3((NN + 127) / 128, GN / 128, KHOP), 256>>>();
    scanA_kernel<<<SCAN_BLOCKS, 1024>>>();
    scanB_kernel<<<1, 256>>>();
    scanC_kernel<<<SCAN_BLOCKS, 1024>>>();
    build_kernel<<<dim3((EE / 4 + 255) / 256, KHOP), 256>>>(kel);
    aggregate_fused_kernel<<<dim3((NN + 7) / 8, 2), 256>>>(out);
}

// round 17
// speedup vs baseline: 1.1075x; 1.0201x over previous
#include <cuda_runtime.h>
#include <cuda_bf16.h>
#include <cuda_fp16.h>
#include <math.h>
#include <stdint.h>

#define NN 50000
#define EE 1600000
#define FF 256
#define KHOP 3
#define GN 256
#define TOTN (KHOP * NN)          // 150000
#define SCAN_BLOCKS ((TOTN + 1023) / 1024)   // 147

// ---------------- scratch (device globals; no allocations allowed) ----------------
__device__ float g_u[KHOP * FF];
__device__ float g_v[KHOP * FF];
__device__ float g_s_src[KHOP * NN];
__device__ float g_s_dst[KHOP * NN];
__device__ int   g_deg[KHOP * NN];
__device__ int   g_ptr[KHOP * NN];
__device__ int   g_fill[KHOP * NN];
__device__ int   g_bsum[SCAN_BLOCKS];
__device__ int   g_boff[SCAN_BLOCKS];
__device__ int2  g_csr[(size_t)KHOP * EE + 32];      // (dst, w-as-int); +32 pad for warp over-read
__device__ __half g_Yh[(size_t)KHOP * NN * FF];      // Y_z = X @ W_z, fp16
__device__ __half g_Xh[(size_t)NN * FF];             // X in fp16
__device__ __half g_Wth[KHOP * FF * GN];             // W transposed [z][n][k], fp16

__device__ __forceinline__ float elu1(float x) { return x > 0.f ? x : expm1f(x); }

// ---------------- small kernels (pipeline front) ----------------

__global__ void zero_kernel() {
    int i = blockIdx.x * blockDim.x + threadIdx.x;
    if (i < TOTN) g_deg[i] = 0;
}

__global__ void uv_kernel(const float* __restrict__ W, const float* __restrict__ a) {
    int z = blockIdx.x;
    int k = threadIdx.x;
    const float* wrow = W + (size_t)(z * FF + k) * GN;
    const float* au = a + z * 2 * FF;
    const float* av = au + FF;
    float u = 0.f, v = 0.f;
    #pragma unroll 8
    for (int j = 0; j < FF; j++) {
        float w = wrow[j];
        u = fmaf(w, au[j], u);
        v = fmaf(w, av[j], v);
    }
    g_u[z * FF + k] = u;
    g_v[z * FF + k] = v;
}

__device__ __forceinline__ uint32_t pkh2(float a, float b) {
    __half2 t = __floats2half2_rn(a, b);
    return *(uint32_t*)&t;
}

// fused: per-hop s_src/s_dst + fp16 conversion of X.
// warp per node; lane owns feature PAIRS {2*lane + 64*j}; float2 LDS (conflict-free).
__global__ void __launch_bounds__(256) scores_convX_kernel(const float* __restrict__ X) {
    __shared__ float su[KHOP][FF];
    __shared__ float sv[KHOP][FF];
    int tid = threadIdx.x;
    for (int i = tid; i < KHOP * FF; i += 256) {
        su[i / FF][i % FF] = g_u[i];
        sv[i / FF][i % FF] = g_v[i];
    }
    __syncthreads();
    int warp = tid >> 5, lane = tid & 31;
    int n = blockIdx.x * 8 + warp;
    if (n >= NN) return;
    const int f0 = lane * 2;
    float2 xp[4];
    #pragma unroll
    for (int j = 0; j < 4; j++) {
        xp[j] = *(const float2*)(X + (size_t)n * FF + f0 + j * 64);
        *(uint32_t*)(g_Xh + (size_t)n * FF + f0 + j * 64) = pkh2(xp[j].x, xp[j].y);
    }
    #pragma unroll
    for (int z = 0; z < KHOP; z++) {
        float du = 0.f, dv = 0.f;
        #pragma unroll
        for (int j = 0; j < 4; j++) {
            int f = f0 + j * 64;
            float2 uu = *(const float2*)&su[z][f];
            float2 vv = *(const float2*)&sv[z][f];
            du = fmaf(xp[j].x, uu.x, du);
            du = fmaf(xp[j].y, uu.y, du);
            dv = fmaf(xp[j].x, vv.x, dv);
            dv = fmaf(xp[j].y, vv.y, dv);
        }
        #pragma unroll
        for (int off = 16; off > 0; off >>= 1) {
            du += __shfl_xor_sync(0xFFFFFFFFu, du, off);
            dv += __shfl_xor_sync(0xFFFFFFFFu, dv, off);
        }
        if (lane == 0) {
            g_s_src[z * NN + n] = du;
            g_s_dst[z * NN + n] = dv;
        }
    }
}

// 4 edges per thread via int4 (EE divisible by 4)
__global__ void hist_kernel(const int* __restrict__ kel) {
    int z = blockIdx.y;
    int e = (blockIdx.x * 256 + threadIdx.x) * 4;
    if (e >= EE) return;
    int4 s = __ldcs((const int4*)(kel + (size_t)z * 2 * EE + e));
    atomicAdd(&g_deg[z * NN + s.x], 1);
    atomicAdd(&g_deg[z * NN + s.y], 1);
    atomicAdd(&g_deg[z * NN + s.z], 1);
    atomicAdd(&g_deg[z * NN + s.w], 1);
}

// ---- 3-phase parallel scan over the whole 150K degree array ----
__global__ void __launch_bounds__(1024) scanA_kernel() {
    __shared__ int wsum[32];
    int b = blockIdx.x, tid = threadIdx.x, lane = tid & 31, wid = tid >> 5;
    int i = b * 1024 + tid;
    int v = (i < TOTN) ? g_deg[i] : 0;
    int x = v;
    #pragma unroll
    for (int off = 1; off < 32; off <<= 1) {
        int t = __shfl_up_sync(0xFFFFFFFFu, x, off);
        if (lane >= off) x += t;
    }
    if (lane == 31) wsum[wid] = x;
    __syncthreads();
    if (wid == 0) {
        int s = wsum[lane];
        #pragma unroll
        for (int off = 1; off < 32; off <<= 1) {
            int t = __shfl_up_sync(0xFFFFFFFFu, s, off);
            if (lane >= off) s += t;
        }
        wsum[lane] = s;
    }
    __syncthreads();
    int woff = wid ? wsum[wid - 1] : 0;
    if (i < TOTN) g_ptr[i] = woff + x - v;
    if (tid == 1023) g_bsum[b] = wsum[31];
}

__global__ void __launch_bounds__(256) scanB_kernel() {
    __shared__ int wsum[8];
    int tid = threadIdx.x, lane = tid & 31, wid = tid >> 5;
    int v = (tid < SCAN_BLOCKS) ? g_bsum[tid] : 0;
    int x = v;
    #pragma unroll
    for (int off = 1; off < 32; off <<= 1) {
        int t = __shfl_up_sync(0xFFFFFFFFu, x, off);
        if (lane >= off) x += t;
    }
    if (lane == 31) wsum[wid] = x;
    __syncthreads();
    if (wid == 0 && lane < 8) {
        int s = wsum[lane];
        #pragma unroll
        for (int off = 1; off < 8; off <<= 1) {
            int t = __shfl_up_sync(0xFFu, s, off);
            if (lane >= off) s += t;
        }
        wsum[lane] = s;
    }
    __syncthreads();
    int woff = wid ? wsum[wid - 1] : 0;
    if (tid < SCAN_BLOCKS) g_boff[tid] = woff + x - v;
}

__global__ void __launch_bounds__(1024) scanC_kernel() {
    int b = blockIdx.x;
    int i = b * 1024 + threadIdx.x;
    if (i >= TOTN) return;
    int z = (i >= 2 * NN) ? 2 : (i >= NN) ? 1 : 0;
    int val = g_ptr[i] + g_boff[b] - z * EE;
    g_ptr[i] = val;
    g_fill[i] = val;
}

// CSR build: 4 edges/thread, int4 index loads, expf weights, int2 entries
__global__ void build_kernel(const int* __restrict__ kel) {
    int z = blockIdx.y;
    int e = (blockIdx.x * 256 + threadIdx.x) * 4;
    if (e >= EE) return;
    int4 s4 = __ldcs((const int4*)(kel + (size_t)z * 2 * EE + e));
    int4 d4 = __ldcs((const int4*)(kel + (size_t)z * 2 * EE + EE + e));
    const int srcs[4] = {s4.x, s4.y, s4.z, s4.w};
    const int dsts[4] = {d4.x, d4.y, d4.z, d4.w};
    #pragma unroll
    for (int q = 0; q < 4; q++) {
        float sc = g_s_src[z * NN + srcs[q]] + g_s_dst[z * NN + dsts[q]];
        float l = sc > 0.f ? sc : 0.2f * sc;       // leaky_relu(alpha=0.2)
        float w = expf(-l);
        int idx = atomicAdd(&g_fill[z * NN + srcs[q]], 1);
        __stcs(&g_csr[(size_t)z * EE + idx], make_int2(dsts[q], __float_as_int(w)));
    }
}

__global__ void __launch_bounds__(256) convW_kernel(const float* __restrict__ W) {
    int idx = blockIdx.x * 256 + threadIdx.x;
    if (idx >= KHOP * FF * GN) return;
    int z = idx >> 16;
    int rem = idx & 65535;
    int k = rem >> 8;
    int n = rem & 255;
    float w = W[(size_t)(z * FF + k) * GN + n];
    g_Wth[z * 65536 + n * 256 + k] = __float2half_rn(w);
}

// ---------------- mma.sync fp16 GEMM, cp.async double-buffered ----------------

#define SAW 40   // smem row pitch in halfs (80 B: 16B-aligned, conflict-free frag reads)

__device__ __forceinline__ void mma16816h(float* c, const uint32_t* a, const uint32_t* b) {
    asm volatile(
        "mma.sync.aligned.m16n8k16.row.col.f32.f16.f16.f32 "
        "{%0,%1,%2,%3}, {%4,%5,%6,%7}, {%8,%9}, {%0,%1,%2,%3};"
        : "+f"(c[0]), "+f"(c[1]), "+f"(c[2]), "+f"(c[3])
        : "r"(a[0]), "r"(a[1]), "r"(a[2]), "r"(a[3]), "r"(b[0]), "r"(b[1]));
}

__device__ __forceinline__ void cp16(uint32_t dsm, const void* gsrc, int srcBytes) {
    asm volatile("cp.async.ca.shared.global [%0], [%1], 16, %2;"
                 :: "r"(dsm), "l"(gsrc), "r"(srcBytes));
}

__global__ void __launch_bounds__(256) gemm_mma_kernel() {
    __shared__ __half sA[2][128 * SAW];
    __shared__ __half sB[2][128 * SAW];

    const int tid = threadIdx.x;
    const int wid = tid >> 5, lane = tid & 31;
    const int g = lane >> 2, tg = lane & 3;
    const int warp_m = wid >> 2;
    const int warp_n = wid & 3;
    const int rowBase = blockIdx.x * 128;
    const int colBase = blockIdx.y * 128;
    const int z = blockIdx.z;

    const __half* Wth = g_Wth + (size_t)z * 65536;
    __half* Yh = g_Yh + (size_t)z * NN * FF;

    // per-thread load coords (2 x 16B per tile per thread)
    int lr[2], ls[2];
    #pragma unroll
    for (int it = 0; it < 2; it++) {
        int q = tid + it * 256;
        lr[it] = q >> 2;
        ls[it] = q & 3;
    }

    auto loadTile = [&](int kc, int buf) {
        const int k0g = kc * 32;
        #pragma unroll
        for (int it = 0; it < 2; it++) {
            int r = lr[it], s = ls[it];
            int row_g = rowBase + r;
            int okA = (row_g < NN);
            const __half* ga = g_Xh + (size_t)(okA ? row_g : 0) * FF + k0g + s * 8;
            cp16((uint32_t)__cvta_generic_to_shared(&sA[buf][r * SAW + s * 8]), ga, okA ? 16 : 0);
            const __half* gb = Wth + (size_t)(colBase + r) * 256 + k0g + s * 8;
            cp16((uint32_t)__cvta_generic_to_shared(&sB[buf][r * SAW + s * 8]), gb, 16);
        }
        asm volatile("cp.async.commit_group;");
    };

    float c[4][4][4];
    #pragma unroll
    for (int mt = 0; mt < 4; mt++)
        #pragma unroll
        for (int nt = 0; nt < 4; nt++)
            #pragma unroll
            for (int q = 0; q < 4; q++) c[mt][nt][q] = 0.f;

    loadTile(0, 0);

    for (int kc = 0; kc < 8; kc++) {
        const int buf = kc & 1;
        if (kc + 1 < 8) {
            loadTile(kc + 1, buf ^ 1);
            asm volatile("cp.async.wait_group 1;");
        } else {
            asm volatile("cp.async.wait_group 0;");
        }
        __syncthreads();

        #pragma unroll
        for (int ks = 0; ks < 2; ks++) {
            const int k0 = ks * 16;
            uint32_t ah[4][4];
            #pragma unroll
            for (int mt = 0; mt < 4; mt++) {
                int r0 = warp_m * 64 + mt * 16 + g;
                int kk = k0 + tg * 2;
                ah[mt][0] = *(const uint32_t*)(sA[buf] + r0 * SAW + kk);
                ah[mt][1] = *(const uint32_t*)(sA[buf] + (r0 + 8) * SAW + kk);
                ah[mt][2] = *(const uint32_t*)(sA[buf] + r0 * SAW + kk + 8);
                ah[mt][3] = *(const uint32_t*)(sA[buf] + (r0 + 8) * SAW + kk + 8);
            }
            uint32_t bh[4][2];
            #pragma unroll
            for (int nt = 0; nt < 4; nt++) {
                int n0 = warp_n * 32 + nt * 8 + g;
                int kk = k0 + tg * 2;
                bh[nt][0] = *(const uint32_t*)(sB[buf] + n0 * SAW + kk);
                bh[nt][1] = *(const uint32_t*)(sB[buf] + n0 * SAW + kk + 8);
            }
            #pragma unroll
            for (int mt = 0; mt < 4; mt++)
                #pragma unroll
                for (int nt = 0; nt < 4; nt++)
                    mma16816h(c[mt][nt], ah[mt], bh[nt]);
        }
        __syncthreads();
    }

    #pragma unroll
    for (int mt = 0; mt < 4; mt++) {
        int r0 = rowBase + warp_m * 64 + mt * 16 + g;
        #pragma unroll
        for (int nt = 0; nt < 4; nt++) {
            int col = colBase + warp_n * 32 + nt * 8 + tg * 2;
            if (r0 < NN)
                *(uint32_t*)(Yh + (size_t)r0 * GN + col) = pkh2(c[mt][nt][0], c[mt][nt][1]);
            if (r0 + 8 < NN)
                *(uint32_t*)(Yh + (size_t)(r0 + 8) * GN + col) = pkh2(c[mt][nt][2], c[mt][nt][3]);
        }
    }
}

// ---------------- fused 3-hop aggregation, feature-split into 2 passes ----------------
__global__ void __launch_bounds__(256) aggregate_fused_kernel(float* __restrict__ out) {
    const int wid = threadIdx.x >> 5, lane = threadIdx.x & 31;
    const int n = blockIdx.x * 8 + wid;
    const int p = blockIdx.y;                    // feature half
    if (n >= NN) return;
    const int fo = p * 128 + lane * 4;

    float tot[4] = {0.f, 0.f, 0.f, 0.f};

    #pragma unroll
    for (int z = 0; z < KHOP; z++) {
        const int start = g_ptr[z * NN + n];
        const int d     = g_deg[z * NN + n];
        const int2* __restrict__ ce = g_csr + (size_t)z * EE + start;
        const __half* __restrict__ Yz = g_Yh + (size_t)z * NN * FF + fo;

        float acc[4] = {0.f, 0.f, 0.f, 0.f};
        float accw = 0.f;

        for (int base = 0; base < d; base += 32) {
            int cnt = min(32, d - base);
            int2 e = __ldcs(&ce[base + lane]);   // streaming: don't evict hot Y
            #pragma unroll 8
            for (int k = 0; k < cnt; k++) {
                int   dst = __shfl_sync(0xFFFFFFFFu, e.x, k);
                float w   = __int_as_float(__shfl_sync(0xFFFFFFFFu, e.y, k));
                accw += w;
                uint2 v = *(const uint2*)(Yz + (size_t)dst * FF);
                float2 f0 = __half22float2(*(__half2*)&v.x);
                float2 f1 = __half22float2(*(__half2*)&v.y);
                acc[0] = fmaf(w, f0.x, acc[0]);
                acc[1] = fmaf(w, f0.y, acc[1]);
                acc[2] = fmaf(w, f1.x, acc[2]);
                acc[3] = fmaf(w, f1.y, acc[3]);
            }
        }
        const float coef = (z == 0) ? 0.5f : (z == 1) ? 0.25f : 0.125f;
        float s = coef / accw;
        #pragma unroll
        for (int t = 0; t < 4; t++) tot[t] = fmaf(acc[t], s, tot[t]);
    }

    float4 o = make_float4(elu1(tot[0]), elu1(tot[1]), elu1(tot[2]), elu1(tot[3]));
    __stcs((float4*)(out + (size_t)n * FF + fo), o);
}

// ---------------- launch (serial; fork proved worthless — shared LTS bound) --------
extern "C" void kernel_launch(void* const* d_in, const int* in_sizes, int n_in,
                              void* d_out, int out_size) {
    const float* X   = (const float*)d_in[0];
    const int*   kel = (const int*)d_in[1];
    const float* W   = (const float*)d_in[2];
    const float* a   = (const float*)d_in[3];
    float* out = (float*)d_out;

    zero_kernel<<<(TOTN + 255) / 256, 256>>>();
    uv_kernel<<<KHOP, 256>>>(W, a);
    convW_kernel<<<(KHOP * FF * GN + 255) / 256, 256>>>(W);
    scores_convX_kernel<<<(NN + 7) / 8, 256>>>(X);
    hist_kernel<<<dim3((EE / 4 + 255) / 256, KHOP), 256>>>(kel);
    gemm_mma_kernel<<<dim3((NN + 127) / 128, GN / 128, KHOP), 256>>>();
    scanA_kernel<<<SCAN_BLOCKS, 1024>>>();
    scanB_kernel<<<1, 256>>>();
    scanC_kernel<<<SCAN_BLOCKS, 1024>>>();
    build_kernel<<<dim3((EE / 4 + 255) / 256, KHOP), 256>>>(kel);
    aggregate_fused_kernel<<<dim3((NN + 7) / 8, 2), 256>>>(out);
}